// round 10
// baseline (speedup 1.0000x reference)
#include <cuda_runtime.h>

#define Hdim 128
#define PREP_BLOCKS 32
#define MAIN_BLOCKS 148
#define MAIN_THREADS 512
#define WARPS_PB (MAIN_THREADS / 32)

// scratch (no allocations allowed)
__device__ float g_u_part[PREP_BLOCKS][Hdim];
__device__ float g_c_part[PREP_BLOCKS];
__device__ double g_sum;
__device__ unsigned long long g_maxkey;
__device__ unsigned g_count;

struct f8 { float a0,a1,a2,a3,a4,a5,a6,a7; };

// 256-bit feat load, evict_last: 102.4MB sequential set fits ~126MB L2,
// so replays can be served from L2 once resident.
__device__ __forceinline__ f8 ldg_keep8(const float* __restrict__ p) {
    f8 v;
    asm("ld.global.nc.L2::evict_last.v8.b32 {%0,%1,%2,%3,%4,%5,%6,%7}, [%8];"
        : "=f"(v.a0), "=f"(v.a1), "=f"(v.a2), "=f"(v.a3),
          "=f"(v.a4), "=f"(v.a5), "=f"(v.a6), "=f"(v.a7)
        : "l"(p));
    return v;
}

__device__ __forceinline__ void loadrow(const float* __restrict__ feat, int node,
                                        int sub, f8& x0, f8& x1, f8& x2, f8& x3)
{
    const float* row = feat + (size_t)node * Hdim;
    x0 = ldg_keep8(row + (sub     ) * 8);
    x1 = ldg_keep8(row + (sub +  4) * 8);
    x2 = ldg_keep8(row + (sub +  8) * 8);
    x3 = ldg_keep8(row + (sub + 12) * 8);
}

__device__ __forceinline__ float dot32(const float* __restrict__ u,
                                       const f8& x0, const f8& x1,
                                       const f8& x2, const f8& x3)
{
    float e0, e1;
    e0 = u[0] * x0.a0;               e1 = u[1] * x0.a1;
    e0 = fmaf(u[2],  x0.a2, e0);     e1 = fmaf(u[3],  x0.a3, e1);
    e0 = fmaf(u[4],  x0.a4, e0);     e1 = fmaf(u[5],  x0.a5, e1);
    e0 = fmaf(u[6],  x0.a6, e0);     e1 = fmaf(u[7],  x0.a7, e1);
    e0 = fmaf(u[8],  x1.a0, e0);     e1 = fmaf(u[9],  x1.a1, e1);
    e0 = fmaf(u[10], x1.a2, e0);     e1 = fmaf(u[11], x1.a3, e1);
    e0 = fmaf(u[12], x1.a4, e0);     e1 = fmaf(u[13], x1.a5, e1);
    e0 = fmaf(u[14], x1.a6, e0);     e1 = fmaf(u[15], x1.a7, e1);
    e0 = fmaf(u[16], x2.a0, e0);     e1 = fmaf(u[17], x2.a1, e1);
    e0 = fmaf(u[18], x2.a2, e0);     e1 = fmaf(u[19], x2.a3, e1);
    e0 = fmaf(u[20], x2.a4, e0);     e1 = fmaf(u[21], x2.a5, e1);
    e0 = fmaf(u[22], x2.a6, e0);     e1 = fmaf(u[23], x2.a7, e1);
    e0 = fmaf(u[24], x3.a0, e0);     e1 = fmaf(u[25], x3.a1, e1);
    e0 = fmaf(u[26], x3.a2, e0);     e1 = fmaf(u[27], x3.a3, e1);
    e0 = fmaf(u[28], x3.a4, e0);     e1 = fmaf(u[29], x3.a5, e1);
    e0 = fmaf(u[30], x3.a6, e0);     e1 = fmaf(u[31], x3.a7, e1);
    return e0 + e1;
}

// ---------------------------------------------------------------------------
// K1 (prep): unchanged. 32 blocks x 128 threads.
// ---------------------------------------------------------------------------
__global__ void __launch_bounds__(128) k_prep(const float* __restrict__ feat,
                                              const float* __restrict__ W1,
                                              const float* __restrict__ b1,
                                              const float* __restrict__ W2,
                                              const float* __restrict__ b2,
                                              const int*   __restrict__ prev)
{
    __shared__ float sphi[16];

    const int lane = threadIdx.x & 31;
    const int warp = threadIdx.x >> 5;
    const int j0   = blockIdx.x * 16;
    const int p    = prev[0];

    const float4 x = ((const float4*)(feat + (size_t)p * Hdim))[lane];

#pragma unroll
    for (int jj = 0; jj < 4; jj++) {
        const int j = j0 + warp * 4 + jj;
        const float4 w = ((const float4*)(W1 + (size_t)j * Hdim))[lane];
        float d = fmaf(w.x, x.x, fmaf(w.y, x.y, fmaf(w.z, x.z, w.w * x.w)));
        d += __shfl_xor_sync(0xffffffffu, d, 16);
        d += __shfl_xor_sync(0xffffffffu, d, 8);
        d += __shfl_xor_sync(0xffffffffu, d, 4);
        d += __shfl_xor_sync(0xffffffffu, d, 2);
        d += __shfl_xor_sync(0xffffffffu, d, 1);
        if (lane == 0) sphi[warp * 4 + jj] = d + b1[j];
    }
    __syncthreads();

    const int h = threadIdx.x;
    float acc = 0.0f;
#pragma unroll
    for (int jj = 0; jj < 16; jj++) {
        acc = fmaf(sphi[jj], W2[(size_t)(j0 + jj) * Hdim + h], acc);
    }
    g_u_part[blockIdx.x][h] = acc;

    if (threadIdx.x == 0) {
        float cp = 0.0f;
#pragma unroll
        for (int jj = 0; jj < 16; jj++) cp = fmaf(sphi[jj], b2[j0 + jj], cp);
        g_c_part[blockIdx.x] = cp;
        if (blockIdx.x == 0) { g_sum = 0.0; g_maxkey = 0ull; g_count = 0u; }
    }
}

// ---------------------------------------------------------------------------
// K2 (main): persistent one wave; STREAM ALL ROWS (no skip). Each warp owns a
// contiguous span of 32-row chunks; 8 consecutive rows per batch (4 lanes per
// row), double-buffered; adj only gates tanh/exp, not loads.
// ---------------------------------------------------------------------------
__global__ void __launch_bounds__(MAIN_THREADS, 1)
k_main(const float* __restrict__ feat,
       const float* __restrict__ adj,
       float* __restrict__ out,
       int N, int out_size)
{
    __shared__ float              su[Hdim];
    __shared__ float              sc;
    __shared__ float              ssum[WARPS_PB];
    __shared__ unsigned long long skey[WARPS_PB];

    const int lane  = threadIdx.x & 31;
    const int wwarp = threadIdx.x >> 5;
    const int gwarp = blockIdx.x * WARPS_PB + wwarp;
    const int nwarp = gridDim.x * WARPS_PB;

    const int chunks_total = (N + 31) >> 5;
    const int cpw  = (chunks_total + nwarp - 1) / nwarp;
    int ci         = gwarp * cpw;
    const int cend = (ci + cpw < chunks_total) ? ci + cpw : chunks_total;

    // first chunk's adj issued before su reads (overlap)
    float a_cur = 0.0f;
    if (ci < cend) {
        const int b0 = ci << 5;
        if (b0 + lane < N) a_cur = __ldg(adj + b0 + lane);
    }

    // Reconstruct u (coalesced across partials)
    if (threadIdx.x < Hdim) {
        float a = 0.0f;
#pragma unroll
        for (int pb = 0; pb < PREP_BLOCKS; pb++) a += g_u_part[pb][threadIdx.x];
        su[threadIdx.x] = a;
    }
    if (threadIdx.x == Hdim) {
        float a = 0.0f;
#pragma unroll
        for (int pb = 0; pb < PREP_BLOCKS; pb++) a += g_c_part[pb];
        sc = a;
    }
    __syncthreads();

    const int sub = lane & 3;    // 8-float slot within row (0..3)
    const int grp = lane >> 2;   // which of 8 concurrent rows (0..7)

    float ureg[32];
#pragma unroll
    for (int t = 0; t < 4; t++)
#pragma unroll
        for (int q = 0; q < 8; q++)
            ureg[t * 8 + q] = su[(sub + 4 * t) * 8 + q];
    const float cc = sc;

    float lsum = 0.0f;
    unsigned long long lkey = 0ull;

    for (; ci < cend; ci++) {
        const int base   = ci << 5;
        const int nvalid = (N - base >= 32) ? 32 : (N - base);

        // prefetch next chunk's adj
        float a_next = 0.0f;
        if (ci + 1 < cend) {
            const int bn = (ci + 1) << 5;
            if (bn + lane < N) a_next = __ldg(adj + bn + lane);
        }

        const unsigned mask = __ballot_sync(0xffffffffu,
                                            a_cur != 0.0f && lane < nvalid);
        if (lane == 0) lsum += (float)(nvalid - __popc(mask));

        // batches of 8 consecutive rows, double-buffered
        int  rA = grp;                 // row offset within chunk
        bool vA = rA < nvalid;
        f8 xA0, xA1, xA2, xA3;
        if (vA) loadrow(feat, base + rA, sub, xA0, xA1, xA2, xA3);

#pragma unroll
        for (int j = 0; j < 32; j += 8) {
            if (j >= nvalid) break;

            const int  rB = j + 8 + grp;
            const bool vB = rB < nvalid;
            f8 xB0, xB1, xB2, xB3;
            if (vB) loadrow(feat, base + rB, sub, xB0, xB1, xB2, xB3);

            float d = vA ? dot32(ureg, xA0, xA1, xA2, xA3) : 0.0f;
            d += __shfl_xor_sync(0xffffffffu, d, 2);
            d += __shfl_xor_sync(0xffffffffu, d, 1);

            if (sub == 0 && vA && ((mask >> rA) & 1u)) {
                const float s    = (d + cc) * 0.04419417382415922f; // 1/sqrt(512)
                const float attn = 10.0f * tanhf(s);
                lsum += expf(attn);
                if (attn != 0.0f) {
                    const unsigned n   = (unsigned)(base + rA);
                    const unsigned b   = __float_as_uint(attn);
                    const unsigned enc = (b & 0x80000000u) ? ~b : (b | 0x80000000u);
                    const unsigned long long key =
                        ((unsigned long long)enc << 32) |
                        (unsigned long long)(0xFFFFFFFFu - n);
                    if (key > lkey) lkey = key;
                }
            }
            rA = rB; vA = vB;
            xA0 = xB0; xA1 = xB1; xA2 = xB2; xA3 = xB3;
        }

        a_cur = a_next;
    }

    // warp-level reduce of lsum / lkey
#pragma unroll
    for (int s = 16; s; s >>= 1) {
        lsum += __shfl_xor_sync(0xffffffffu, lsum, s);
        const unsigned long long o = __shfl_xor_sync(0xffffffffu, lkey, s);
        if (o > lkey) lkey = o;
    }

    if (lane == 0) { ssum[wwarp] = lsum; skey[wwarp] = lkey; }
    __syncthreads();

    if (threadIdx.x == 0) {
        float bs = 0.0f;
        unsigned long long bk = 0ull;
#pragma unroll
        for (int i = 0; i < WARPS_PB; i++) {
            bs += ssum[i];
            if (skey[i] > bk) bk = skey[i];
        }
        atomicAdd(&g_sum, (double)bs);
        atomicMax(&g_maxkey, bk);
        __threadfence();
        const unsigned done = atomicAdd(&g_count, 1u);
        if (done == gridDim.x - 1u) {
            const double total = atomicAdd(&g_sum, 0.0);
            const unsigned long long k = atomicMax(&g_maxkey, 0ull);
            float pidx = 0.0f, pval = 0.0f;
            if (k != 0ull) {
                const unsigned enc = (unsigned)(k >> 32);
                const unsigned bb  = (enc & 0x80000000u) ? (enc ^ 0x80000000u) : ~enc;
                const float amax   = __uint_as_float(bb);
                const int   idx    = (int)(0xFFFFFFFFu - (unsigned)(k & 0xFFFFFFFFull));
                pidx = (float)idx;
                pval = (float)(exp((double)amax) / total);
            }
            out[0] = pidx;
            if (out_size > 1) out[1] = pval;
        }
    }
}

// ---------------------------------------------------------------------------
// inputs (metadata order): output[N,128], adj[N], W1[512,128], b1[512],
//                          W2[512,128], b2[512], prev_node (int scalar)
// ---------------------------------------------------------------------------
extern "C" void kernel_launch(void* const* d_in, const int* in_sizes, int n_in,
                              void* d_out, int out_size)
{
    const float* feat = (const float*)d_in[0];
    const float* adj  = (const float*)d_in[1];
    const float* W1   = (const float*)d_in[2];
    const float* b1   = (const float*)d_in[3];
    const float* W2   = (const float*)d_in[4];
    const float* b2   = (const float*)d_in[5];
    const int*   prev = (const int*)d_in[6];
    float* out = (float*)d_out;

    const int N = in_sizes[1];   // adj has N elements

    k_prep<<<PREP_BLOCKS, 128>>>(feat, W1, b1, W2, b2, prev);
    k_main<<<MAIN_BLOCKS, MAIN_THREADS>>>(feat, adj, out, N, out_size);
}

// round 11
// speedup vs baseline: 1.7858x; 1.7858x over previous
#include <cuda_runtime.h>

#define Hdim 128
#define PREP_BLOCKS 32
#define MAIN_BLOCKS 148
#define MAIN_THREADS 512
#define WARPS_PB (MAIN_THREADS / 32)

// scratch (no allocations allowed)
__device__ float g_u_part[PREP_BLOCKS][Hdim];
__device__ float g_c_part[PREP_BLOCKS];
__device__ double g_sum;
__device__ unsigned long long g_maxkey;
__device__ unsigned g_count;
__device__ unsigned g_prep_done;

struct f8 { float a0,a1,a2,a3,a4,a5,a6,a7; };

__device__ __forceinline__ f8 ldg_keep8(const float* __restrict__ p) {
    f8 v;
    asm("ld.global.nc.L2::evict_last.v8.b32 {%0,%1,%2,%3,%4,%5,%6,%7}, [%8];"
        : "=f"(v.a0), "=f"(v.a1), "=f"(v.a2), "=f"(v.a3),
          "=f"(v.a4), "=f"(v.a5), "=f"(v.a6), "=f"(v.a7)
        : "l"(p));
    return v;
}

__device__ __forceinline__ void loadrow(const float* __restrict__ feat, int node,
                                        int sub, f8& x0, f8& x1, f8& x2, f8& x3)
{
    const float* row = feat + (size_t)node * Hdim;
    x0 = ldg_keep8(row + (sub     ) * 8);
    x1 = ldg_keep8(row + (sub +  4) * 8);
    x2 = ldg_keep8(row + (sub +  8) * 8);
    x3 = ldg_keep8(row + (sub + 12) * 8);
}

__device__ __forceinline__ float dot32(const float* __restrict__ u,
                                       const f8& x0, const f8& x1,
                                       const f8& x2, const f8& x3)
{
    float e0, e1;
    e0 = u[0] * x0.a0;               e1 = u[1] * x0.a1;
    e0 = fmaf(u[2],  x0.a2, e0);     e1 = fmaf(u[3],  x0.a3, e1);
    e0 = fmaf(u[4],  x0.a4, e0);     e1 = fmaf(u[5],  x0.a5, e1);
    e0 = fmaf(u[6],  x0.a6, e0);     e1 = fmaf(u[7],  x0.a7, e1);
    e0 = fmaf(u[8],  x1.a0, e0);     e1 = fmaf(u[9],  x1.a1, e1);
    e0 = fmaf(u[10], x1.a2, e0);     e1 = fmaf(u[11], x1.a3, e1);
    e0 = fmaf(u[12], x1.a4, e0);     e1 = fmaf(u[13], x1.a5, e1);
    e0 = fmaf(u[14], x1.a6, e0);     e1 = fmaf(u[15], x1.a7, e1);
    e0 = fmaf(u[16], x2.a0, e0);     e1 = fmaf(u[17], x2.a1, e1);
    e0 = fmaf(u[18], x2.a2, e0);     e1 = fmaf(u[19], x2.a3, e1);
    e0 = fmaf(u[20], x2.a4, e0);     e1 = fmaf(u[21], x2.a5, e1);
    e0 = fmaf(u[22], x2.a6, e0);     e1 = fmaf(u[23], x2.a7, e1);
    e0 = fmaf(u[24], x3.a0, e0);     e1 = fmaf(u[25], x3.a1, e1);
    e0 = fmaf(u[26], x3.a2, e0);     e1 = fmaf(u[27], x3.a3, e1);
    e0 = fmaf(u[28], x3.a4, e0);     e1 = fmaf(u[29], x3.a5, e1);
    e0 = fmaf(u[30], x3.a6, e0);     e1 = fmaf(u[31], x3.a7, e1);
    return e0 + e1;
}

// ---------------------------------------------------------------------------
// Fused persistent kernel: one launch, one wave (148 x 512, all resident).
// Blocks 0-31: prep (phi1 -> u_part/c_part), flag via g_prep_done.
// All blocks: prefetch adj, spin on flag, reconstruct u, scattered-skip
// main loop (R9 structure), block reduce, last block finalizes + resets flag.
// ---------------------------------------------------------------------------
__global__ void __launch_bounds__(MAIN_THREADS, 1)
k_fused(const float* __restrict__ feat,
        const float* __restrict__ adj,
        const float* __restrict__ W1,
        const float* __restrict__ b1,
        const float* __restrict__ W2,
        const float* __restrict__ b2,
        const int*   __restrict__ prev,
        float* __restrict__ out,
        int N, int out_size)
{
    __shared__ float              sphi[16];
    __shared__ float              su[Hdim];
    __shared__ float              sc;
    __shared__ float              ssum[WARPS_PB];
    __shared__ unsigned long long skey[WARPS_PB];

    const int lane  = threadIdx.x & 31;
    const int wwarp = threadIdx.x >> 5;
    const int gwarp = blockIdx.x * WARPS_PB + wwarp;
    const int nwarp = MAIN_BLOCKS * WARPS_PB;

    // issue first adj prefetch before anything else (overlaps prep/spin)
    int  c    = gwarp;
    int  base = c * 32;
    float a_cur = 0.0f;
    if (base + lane < N) a_cur = __ldg(adj + base + lane);

    // ---- prep: blocks 0..31 compute their 16 phi1 entries + partials ----
    if (blockIdx.x < PREP_BLOCKS) {
        const int j0 = blockIdx.x * 16;
        if (threadIdx.x < 128) {
            const int p = prev[0];
            const float4 x = ((const float4*)(feat + (size_t)p * Hdim))[lane];
#pragma unroll
            for (int jj = 0; jj < 4; jj++) {
                const int j = j0 + wwarp * 4 + jj;   // wwarp 0..3 here
                const float4 w = ((const float4*)(W1 + (size_t)j * Hdim))[lane];
                float d = fmaf(w.x, x.x, fmaf(w.y, x.y, fmaf(w.z, x.z, w.w * x.w)));
                d += __shfl_xor_sync(0xffffffffu, d, 16);
                d += __shfl_xor_sync(0xffffffffu, d, 8);
                d += __shfl_xor_sync(0xffffffffu, d, 4);
                d += __shfl_xor_sync(0xffffffffu, d, 2);
                d += __shfl_xor_sync(0xffffffffu, d, 1);
                if (lane == 0) sphi[wwarp * 4 + jj] = d + b1[j];
            }
        }
        __syncthreads();
        if (threadIdx.x < 128) {
            const int h = threadIdx.x;
            float acc = 0.0f;
#pragma unroll
            for (int jj = 0; jj < 16; jj++)
                acc = fmaf(sphi[jj], W2[(size_t)(j0 + jj) * Hdim + h], acc);
            g_u_part[blockIdx.x][h] = acc;
            if (h == 0) {
                float cp = 0.0f;
#pragma unroll
                for (int jj = 0; jj < 16; jj++) cp = fmaf(sphi[jj], b2[j0 + jj], cp);
                g_c_part[blockIdx.x] = cp;
                if (blockIdx.x == 0) { g_sum = 0.0; g_maxkey = 0ull; g_count = 0u; }
            }
        }
        __syncthreads();
        if (threadIdx.x == 0) {
            __threadfence();
            atomicAdd(&g_prep_done, 1u);
        }
    }

    // ---- spin until all 32 prep partials are published ----
    if (threadIdx.x == 0) {
        while (atomicAdd(&g_prep_done, 0u) < PREP_BLOCKS) { }
    }
    __syncthreads();
    __threadfence();

    // ---- reconstruct u ----
    if (threadIdx.x < Hdim) {
        float a = 0.0f;
#pragma unroll
        for (int pb = 0; pb < PREP_BLOCKS; pb++) a += g_u_part[pb][threadIdx.x];
        su[threadIdx.x] = a;
    }
    if (threadIdx.x == Hdim) {
        float a = 0.0f;
#pragma unroll
        for (int pb = 0; pb < PREP_BLOCKS; pb++) a += g_c_part[pb];
        sc = a;
    }
    __syncthreads();

    const int sub = lane & 3;    // 8-float slot within row (0..3)
    const int grp = lane >> 2;   // which of 8 concurrent rows (0..7)

    float ureg[32];
#pragma unroll
    for (int t = 0; t < 4; t++)
#pragma unroll
        for (int q = 0; q < 8; q++)
            ureg[t * 8 + q] = su[(sub + 4 * t) * 8 + q];
    const float cc = sc;

    float lsum = 0.0f;
    unsigned long long lkey = 0ull;

    // ---- main loop: grid-stride 32-node chunks, skip masked rows ----
    while (base < N) {
        const int cn    = c + nwarp;
        const int basen = cn * 32;
        float a_next = 0.0f;
        if (basen < N && basen + lane < N) a_next = __ldg(adj + basen + lane);

        const unsigned mask = __ballot_sync(0xffffffffu, a_cur != 0.0f);
        const int m      = __popc(mask);
        const int nvalid = (N - base >= 32) ? 32 : (N - base);
        if (lane == 0) lsum += (float)(nvalid - m);   // exp(0) per masked node

        int rA = (int)__fns(mask, 0, grp + 1);
        f8 xA0, xA1, xA2, xA3;
        if (rA >= 0) loadrow(feat, base + rA, sub, xA0, xA1, xA2, xA3);

        for (int j = 0; j < m; j += 8) {
            const int rB = (int)__fns(mask, 0, j + 8 + grp + 1);
            f8 xB0, xB1, xB2, xB3;
            if (rB >= 0) loadrow(feat, base + rB, sub, xB0, xB1, xB2, xB3);

            float d = (rA >= 0) ? dot32(ureg, xA0, xA1, xA2, xA3) : 0.0f;
            d += __shfl_xor_sync(0xffffffffu, d, 2);
            d += __shfl_xor_sync(0xffffffffu, d, 1);

            if (sub == 0 && rA >= 0) {
                const float s    = (d + cc) * 0.04419417382415922f; // 1/sqrt(512)
                const float attn = 10.0f * tanhf(s);
                lsum += expf(attn);
                if (attn != 0.0f) {
                    const unsigned n   = (unsigned)(base + rA);
                    const unsigned b   = __float_as_uint(attn);
                    const unsigned enc = (b & 0x80000000u) ? ~b : (b | 0x80000000u);
                    const unsigned long long key =
                        ((unsigned long long)enc << 32) |
                        (unsigned long long)(0xFFFFFFFFu - n);
                    if (key > lkey) lkey = key;
                }
            }
            rA  = rB;
            xA0 = xB0; xA1 = xB1; xA2 = xB2; xA3 = xB3;
        }

        a_cur = a_next;
        c     = cn;
        base  = basen;
    }

    // ---- reductions + finalize ----
#pragma unroll
    for (int s = 16; s; s >>= 1) {
        lsum += __shfl_xor_sync(0xffffffffu, lsum, s);
        const unsigned long long o = __shfl_xor_sync(0xffffffffu, lkey, s);
        if (o > lkey) lkey = o;
    }

    if (lane == 0) { ssum[wwarp] = lsum; skey[wwarp] = lkey; }
    __syncthreads();

    if (threadIdx.x == 0) {
        float bs = 0.0f;
        unsigned long long bk = 0ull;
#pragma unroll
        for (int i = 0; i < WARPS_PB; i++) {
            bs += ssum[i];
            if (skey[i] > bk) bk = skey[i];
        }
        atomicAdd(&g_sum, (double)bs);
        atomicMax(&g_maxkey, bk);
        __threadfence();
        const unsigned done = atomicAdd(&g_count, 1u);
        if (done == MAIN_BLOCKS - 1u) {
            const double total = atomicAdd(&g_sum, 0.0);
            const unsigned long long k = atomicMax(&g_maxkey, 0ull);
            float pidx = 0.0f, pval = 0.0f;
            if (k != 0ull) {
                const unsigned enc = (unsigned)(k >> 32);
                const unsigned bb  = (enc & 0x80000000u) ? (enc ^ 0x80000000u) : ~enc;
                const float amax   = __uint_as_float(bb);
                const int   idx    = (int)(0xFFFFFFFFu - (unsigned)(k & 0xFFFFFFFFull));
                pidx = (float)idx;
                pval = (float)(exp((double)amax) / total);
            }
            out[0] = pidx;
            if (out_size > 1) out[1] = pval;
            g_prep_done = 0u;   // reset for next graph replay
        }
    }
}

// ---------------------------------------------------------------------------
// inputs (metadata order): output[N,128], adj[N], W1[512,128], b1[512],
//                          W2[512,128], b2[512], prev_node (int scalar)
// ---------------------------------------------------------------------------
extern "C" void kernel_launch(void* const* d_in, const int* in_sizes, int n_in,
                              void* d_out, int out_size)
{
    const float* feat = (const float*)d_in[0];
    const float* adj  = (const float*)d_in[1];
    const float* W1   = (const float*)d_in[2];
    const float* b1   = (const float*)d_in[3];
    const float* W2   = (const float*)d_in[4];
    const float* b2   = (const float*)d_in[5];
    const int*   prev = (const int*)d_in[6];
    float* out = (float*)d_out;

    const int N = in_sizes[1];   // adj has N elements

    k_fused<<<MAIN_BLOCKS, MAIN_THREADS>>>(feat, adj, W1, b1, W2, b2, prev,
                                           out, N, out_size);
}

// round 12
// speedup vs baseline: 1.8290x; 1.0242x over previous
#include <cuda_runtime.h>

#define Hdim 128
#define PREP_BLOCKS 32
#define MAIN_BLOCKS 592
#define MAIN_THREADS 256
#define WARPS_PB (MAIN_THREADS / 32)

// scratch (no allocations allowed)
__device__ float g_u_part[PREP_BLOCKS][Hdim];
__device__ float g_c_part[PREP_BLOCKS];
__device__ double g_sum;
__device__ unsigned long long g_maxkey;
__device__ unsigned g_count;

struct f8 { float a0,a1,a2,a3,a4,a5,a6,a7; };

__device__ __forceinline__ f8 ldg8(const float* __restrict__ p) {
    f8 v;
    asm("ld.global.nc.v8.b32 {%0,%1,%2,%3,%4,%5,%6,%7}, [%8];"
        : "=f"(v.a0), "=f"(v.a1), "=f"(v.a2), "=f"(v.a3),
          "=f"(v.a4), "=f"(v.a5), "=f"(v.a6), "=f"(v.a7)
        : "l"(p));
    return v;
}

// ---------------------------------------------------------------------------
// K1 (prep): 32 blocks x 128 threads (unchanged).
// ---------------------------------------------------------------------------
__global__ void __launch_bounds__(128) k_prep(const float* __restrict__ feat,
                                              const float* __restrict__ W1,
                                              const float* __restrict__ b1,
                                              const float* __restrict__ W2,
                                              const float* __restrict__ b2,
                                              const int*   __restrict__ prev)
{
    __shared__ float sphi[16];

    const int lane = threadIdx.x & 31;
    const int warp = threadIdx.x >> 5;
    const int j0   = blockIdx.x * 16;
    const int p    = prev[0];

    const float4 x = ((const float4*)(feat + (size_t)p * Hdim))[lane];

#pragma unroll
    for (int jj = 0; jj < 4; jj++) {
        const int j = j0 + warp * 4 + jj;
        const float4 w = ((const float4*)(W1 + (size_t)j * Hdim))[lane];
        float d = fmaf(w.x, x.x, fmaf(w.y, x.y, fmaf(w.z, x.z, w.w * x.w)));
        d += __shfl_xor_sync(0xffffffffu, d, 16);
        d += __shfl_xor_sync(0xffffffffu, d, 8);
        d += __shfl_xor_sync(0xffffffffu, d, 4);
        d += __shfl_xor_sync(0xffffffffu, d, 2);
        d += __shfl_xor_sync(0xffffffffu, d, 1);
        if (lane == 0) sphi[warp * 4 + jj] = d + b1[j];
    }
    __syncthreads();

    const int h = threadIdx.x;
    float acc = 0.0f;
#pragma unroll
    for (int jj = 0; jj < 16; jj++) {
        acc = fmaf(sphi[jj], W2[(size_t)(j0 + jj) * Hdim + h], acc);
    }
    g_u_part[blockIdx.x][h] = acc;

    if (threadIdx.x == 0) {
        float cp = 0.0f;
#pragma unroll
        for (int jj = 0; jj < 16; jj++) cp = fmaf(sphi[jj], b2[j0 + jj], cp);
        g_c_part[blockIdx.x] = cp;
        if (blockIdx.x == 0) { g_sum = 0.0; g_maxkey = 0ull; g_count = 0u; }
    }
}

// ---------------------------------------------------------------------------
// K2 (main): 592 blocks x 256 threads, 4 blocks/SM (32 warps/SM, regs<=64).
// Per warp: 8 lanes/row, 4 rows/batch double-buffered, scattered-skip chunks.
// ---------------------------------------------------------------------------
__global__ void __launch_bounds__(MAIN_THREADS, 4)
k_main(const float* __restrict__ feat,
       const float* __restrict__ adj,
       float* __restrict__ out,
       int N, int out_size)
{
    __shared__ float              su[Hdim];
    __shared__ float              sc;
    __shared__ float              ssum[WARPS_PB];
    __shared__ unsigned long long skey[WARPS_PB];

    const int lane  = threadIdx.x & 31;
    const int wwarp = threadIdx.x >> 5;
    const int gwarp = blockIdx.x * WARPS_PB + wwarp;
    const int nwarp = MAIN_BLOCKS * WARPS_PB;

    // first chunk's adj issued before su reads (overlap)
    int  c    = gwarp;
    int  base = c * 32;
    float a_cur = 0.0f;
    if (base + lane < N) a_cur = __ldg(adj + base + lane);

    // Reconstruct u (coalesced across partials)
    if (threadIdx.x < Hdim) {
        float a = 0.0f;
#pragma unroll
        for (int pb = 0; pb < PREP_BLOCKS; pb++) a += g_u_part[pb][threadIdx.x];
        su[threadIdx.x] = a;
    }
    if (threadIdx.x == Hdim) {
        float a = 0.0f;
#pragma unroll
        for (int pb = 0; pb < PREP_BLOCKS; pb++) a += g_c_part[pb];
        sc = a;
    }
    __syncthreads();

    const int sub = lane & 7;    // 8-float slot within row (0..7)
    const int grp = lane >> 3;   // which of 4 concurrent rows (0..3)

    // u floats this lane needs: f8 slots sub and sub+8 (of 16)
    float ureg[16];
#pragma unroll
    for (int q = 0; q < 8; q++) {
        ureg[q]     = su[sub * 8 + q];
        ureg[8 + q] = su[(sub + 8) * 8 + q];
    }
    const float cc = sc;

    float lsum = 0.0f;
    unsigned long long lkey = 0ull;

    while (base < N) {
        // prefetch next chunk's adj
        const int cn    = c + nwarp;
        const int basen = cn * 32;
        float a_next = 0.0f;
        if (basen < N && basen + lane < N) a_next = __ldg(adj + basen + lane);

        const unsigned mask = __ballot_sync(0xffffffffu, a_cur != 0.0f);
        const int m      = __popc(mask);
        const int nvalid = (N - base >= 32) ? 32 : (N - base);
        if (lane == 0) lsum += (float)(nvalid - m);   // exp(0) per masked node

        // batches of 4 rows, double-buffered
        int rA = (int)__fns(mask, 0, grp + 1);
        f8 xA0, xA1;
        if (rA >= 0) {
            const float* row = feat + (size_t)(base + rA) * Hdim;
            xA0 = ldg8(row + sub * 8);
            xA1 = ldg8(row + (sub + 8) * 8);
        }

        for (int j = 0; j < m; j += 4) {
            const int rB = (int)__fns(mask, 0, j + 4 + grp + 1);
            f8 xB0, xB1;
            if (rB >= 0) {
                const float* row = feat + (size_t)(base + rB) * Hdim;
                xB0 = ldg8(row + sub * 8);
                xB1 = ldg8(row + (sub + 8) * 8);
            }

            float d = 0.0f;
            if (rA >= 0) {
                float e0, e1;
                e0 = ureg[0] * xA0.a0;            e1 = ureg[1] * xA0.a1;
                e0 = fmaf(ureg[2],  xA0.a2, e0);  e1 = fmaf(ureg[3],  xA0.a3, e1);
                e0 = fmaf(ureg[4],  xA0.a4, e0);  e1 = fmaf(ureg[5],  xA0.a5, e1);
                e0 = fmaf(ureg[6],  xA0.a6, e0);  e1 = fmaf(ureg[7],  xA0.a7, e1);
                e0 = fmaf(ureg[8],  xA1.a0, e0);  e1 = fmaf(ureg[9],  xA1.a1, e1);
                e0 = fmaf(ureg[10], xA1.a2, e0);  e1 = fmaf(ureg[11], xA1.a3, e1);
                e0 = fmaf(ureg[12], xA1.a4, e0);  e1 = fmaf(ureg[13], xA1.a5, e1);
                e0 = fmaf(ureg[14], xA1.a6, e0);  e1 = fmaf(ureg[15], xA1.a7, e1);
                d = e0 + e1;
            }

            // one 3-stage butterfly reduces all 4 rows (8-lane groups)
            d += __shfl_xor_sync(0xffffffffu, d, 4);
            d += __shfl_xor_sync(0xffffffffu, d, 2);
            d += __shfl_xor_sync(0xffffffffu, d, 1);

            if (sub == 0 && rA >= 0) {
                const float s    = (d + cc) * 0.04419417382415922f; // 1/sqrt(512)
                const float attn = 10.0f * tanhf(s);
                lsum += expf(attn);
                if (attn != 0.0f) {
                    const unsigned n   = (unsigned)(base + rA);
                    const unsigned b   = __float_as_uint(attn);
                    const unsigned enc = (b & 0x80000000u) ? ~b : (b | 0x80000000u);
                    const unsigned long long key =
                        ((unsigned long long)enc << 32) |
                        (unsigned long long)(0xFFFFFFFFu - n);
                    if (key > lkey) lkey = key;
                }
            }
            rA  = rB;
            xA0 = xB0; xA1 = xB1;
        }

        a_cur = a_next;
        c     = cn;
        base  = basen;
    }

    // warp-level reduce of lsum / lkey
#pragma unroll
    for (int s = 16; s; s >>= 1) {
        lsum += __shfl_xor_sync(0xffffffffu, lsum, s);
        const unsigned long long o = __shfl_xor_sync(0xffffffffu, lkey, s);
        if (o > lkey) lkey = o;
    }

    if (lane == 0) { ssum[wwarp] = lsum; skey[wwarp] = lkey; }
    __syncthreads();

    if (threadIdx.x == 0) {
        float bs = 0.0f;
        unsigned long long bk = 0ull;
#pragma unroll
        for (int i = 0; i < WARPS_PB; i++) {
            bs += ssum[i];
            if (skey[i] > bk) bk = skey[i];
        }
        atomicAdd(&g_sum, (double)bs);
        atomicMax(&g_maxkey, bk);
        __threadfence();
        const unsigned done = atomicAdd(&g_count, 1u);
        if (done == MAIN_BLOCKS - 1u) {
            const double total = atomicAdd(&g_sum, 0.0);
            const unsigned long long k = atomicMax(&g_maxkey, 0ull);
            float pidx = 0.0f, pval = 0.0f;
            if (k != 0ull) {
                const unsigned enc = (unsigned)(k >> 32);
                const unsigned bb  = (enc & 0x80000000u) ? (enc ^ 0x80000000u) : ~enc;
                const float amax   = __uint_as_float(bb);
                const int   idx    = (int)(0xFFFFFFFFu - (unsigned)(k & 0xFFFFFFFFull));
                pidx = (float)idx;
                pval = (float)(exp((double)amax) / total);
            }
            out[0] = pidx;
            if (out_size > 1) out[1] = pval;
        }
    }
}

// ---------------------------------------------------------------------------
// inputs (metadata order): output[N,128], adj[N], W1[512,128], b1[512],
//                          W2[512,128], b2[512], prev_node (int scalar)
// ---------------------------------------------------------------------------
extern "C" void kernel_launch(void* const* d_in, const int* in_sizes, int n_in,
                              void* d_out, int out_size)
{
    const float* feat = (const float*)d_in[0];
    const float* adj  = (const float*)d_in[1];
    const float* W1   = (const float*)d_in[2];
    const float* b1   = (const float*)d_in[3];
    const float* W2   = (const float*)d_in[4];
    const float* b2   = (const float*)d_in[5];
    const int*   prev = (const int*)d_in[6];
    float* out = (float*)d_out;

    const int N = in_sizes[1];   // adj has N elements

    k_prep<<<PREP_BLOCKS, 128>>>(feat, W1, b1, W2, b2, prev);
    k_main<<<MAIN_BLOCKS, MAIN_THREADS>>>(feat, adj, out, N, out_size);
}